// round 4
// baseline (speedup 1.0000x reference)
#include <cuda_runtime.h>
#include <cuda_bf16.h>

#define N_NODES 10000
#define N_EDGES 640000
#define F_IN 128
#define F_H 128
#define F_OUT 64

// ---------------- scratch (device globals; no allocation allowed) ----------------
__device__ int   g_odd_or;               // 0 after detect => indices are int64
__device__ int   g_deg_in [N_NODES];
__device__ int   g_deg_out[N_NODES];
__device__ float g_rs_in  [N_NODES];
__device__ float g_rs_out [N_NODES];
__device__ int   g_row_ptr[N_NODES + 1];
__device__ int   g_cursor [N_NODES];
__device__ int   g_src_sorted[N_EDGES];
__device__ __align__(16) float g_A1[N_NODES * F_H];    // (X @ W1) * rs_out
__device__ __align__(16) float g_H [N_NODES * F_H];    // layer-1 output (post relu)
__device__ __align__(16) float g_A2[N_NODES * F_OUT];  // (H @ W2) * rs_out

// fetch edge index e from buffer that is either int32 or int64 (little-endian)
__device__ __forceinline__ int idx_at(const int* __restrict__ p, int e) {
    if (g_odd_or == 0) {
        // int64 layout: low word at 2e (values < 2^31, nonnegative)
        return p[2 * e];
    }
    return p[e];
}

// ---------------- dtype detect + degree / CSR build ----------------
__global__ void k_zero_deg() {
    int i = blockIdx.x * blockDim.x + threadIdx.x;
    if (i == 0) g_odd_or = 0;
    if (i < N_NODES) { g_deg_in[i] = 0; g_deg_out[i] = 0; }
}

// OR together the high-half words of the first 2048 candidate int64 elements.
__global__ void k_detect(const int* __restrict__ src) {
    int i = blockIdx.x * blockDim.x + threadIdx.x;   // 2048 threads
    int v = src[2 * i + 1];
    #pragma unroll
    for (int o = 16; o; o >>= 1) v |= __shfl_xor_sync(0xFFFFFFFFu, v, o);
    if ((threadIdx.x & 31) == 0 && v) atomicOr(&g_odd_or, 1);
}

__global__ void k_degrees(const int* __restrict__ src,
                          const int* __restrict__ dst) {
    int e = blockIdx.x * blockDim.x + threadIdx.x;
    if (e < N_EDGES) {
        int s = idx_at(src, e);
        int d = idx_at(dst, e);
        atomicAdd(&g_deg_out[s], 1);
        atomicAdd(&g_deg_in [d], 1);
    }
}

__global__ void k_rsqrt_deg() {
    int i = blockIdx.x * blockDim.x + threadIdx.x;
    if (i < N_NODES) {
        g_rs_in [i] = rsqrtf((float)max(g_deg_in [i], 1));
        g_rs_out[i] = rsqrtf((float)max(g_deg_out[i], 1));
    }
}

// single-block exclusive scan of deg_in -> row_ptr; also seeds cursor
__global__ void k_scan() {
    __shared__ int s[1024];
    __shared__ int carry;
    int tid = threadIdx.x;
    if (tid == 0) { carry = 0; g_row_ptr[0] = 0; }
    __syncthreads();
    for (int base = 0; base < N_NODES; base += 1024) {
        int i = base + tid;
        int v = (i < N_NODES) ? g_deg_in[i] : 0;
        s[tid] = v;
        __syncthreads();
        #pragma unroll
        for (int off = 1; off < 1024; off <<= 1) {
            int t = (tid >= off) ? s[tid - off] : 0;
            __syncthreads();
            s[tid] += t;
            __syncthreads();
        }
        int inc = s[tid] + carry;
        if (i < N_NODES) {
            g_row_ptr[i + 1] = inc;
            g_cursor[i]      = inc - v;   // exclusive prefix
        }
        __syncthreads();
        if (tid == 1023) carry = inc;
        __syncthreads();
    }
}

__global__ void k_fill(const int* __restrict__ src,
                       const int* __restrict__ dst) {
    int e = blockIdx.x * blockDim.x + threadIdx.x;
    if (e < N_EDGES) {
        int d = idx_at(dst, e);
        int p = atomicAdd(&g_cursor[d], 1);
        g_src_sorted[p] = idx_at(src, e);
    }
}

// ---------------- GEMM body: C[m][n] = (sum_k A[m][k]*B[k][n]) * rs_out[m] ----
// BM=64, BN=64, BK=16, 256 threads, 4x4 per thread. N multiple of 64, K of 16.
__device__ __forceinline__ void gemm_rs_body(
    const float* __restrict__ A, const float* __restrict__ B,
    float* __restrict__ C, int M, int N, int K)
{
    __shared__ __align__(16) float As[16][68];   // [BK][BM+4] pad (17*16B rows)
    __shared__ __align__(16) float Bs[16][64];
    int tid = threadIdx.x;
    int tx = tid & 15, ty = tid >> 4;
    int bm = blockIdx.y * 64;
    int bn = blockIdx.x * 64;
    float acc[4][4] = {};
    for (int k0 = 0; k0 < K; k0 += 16) {
        {
            int r = tid >> 2;
            int c = (tid & 3) * 4;
            float4 v = make_float4(0.f, 0.f, 0.f, 0.f);
            if (bm + r < M)
                v = *reinterpret_cast<const float4*>(&A[(size_t)(bm + r) * K + k0 + c]);
            As[c + 0][r] = v.x; As[c + 1][r] = v.y;
            As[c + 2][r] = v.z; As[c + 3][r] = v.w;
        }
        {
            int r = tid >> 4;
            int c = (tid & 15) * 4;
            float4 v = *reinterpret_cast<const float4*>(&B[(size_t)(k0 + r) * N + bn + c]);
            Bs[r][c + 0] = v.x; Bs[r][c + 1] = v.y;
            Bs[r][c + 2] = v.z; Bs[r][c + 3] = v.w;
        }
        __syncthreads();
        #pragma unroll
        for (int k = 0; k < 16; k++) {
            float4 a = *reinterpret_cast<const float4*>(&As[k][ty * 4]);
            float4 b = *reinterpret_cast<const float4*>(&Bs[k][tx * 4]);
            float av[4] = {a.x, a.y, a.z, a.w};
            float bv[4] = {b.x, b.y, b.z, b.w};
            #pragma unroll
            for (int i = 0; i < 4; i++)
                #pragma unroll
                for (int j = 0; j < 4; j++)
                    acc[i][j] += av[i] * bv[j];
        }
        __syncthreads();
    }
    #pragma unroll
    for (int i = 0; i < 4; i++) {
        int m = bm + ty * 4 + i;
        if (m < M) {
            float s = g_rs_out[m];
            float4 o = make_float4(acc[i][0] * s, acc[i][1] * s,
                                   acc[i][2] * s, acc[i][3] * s);
            *reinterpret_cast<float4*>(&C[(size_t)m * N + bn + tx * 4]) = o;
        }
    }
}

__global__ void k_gemm1(const float* __restrict__ X, const float* __restrict__ W1) {
    gemm_rs_body(X, W1, &g_A1[0], N_NODES, F_H, F_IN);
}
__global__ void k_gemm2(const float* __restrict__ W2) {
    gemm_rs_body(&g_H[0], W2, &g_A2[0], N_NODES, F_OUT, F_H);
}

// ---------------- SpMM (CSR gather) + fused epilogue ----------------
// one block per dst row; F threads, thread f sums X[src][f] over in-edges,
// then *rs_in[row] + bias[f] (+relu).
template <int F, bool RELU>
__device__ __forceinline__ void spmm_body(const float* __restrict__ X,
                                          const float* __restrict__ bias,
                                          float* __restrict__ out)
{
    const int row = blockIdx.x;
    const int f   = threadIdx.x;
    const int beg = g_row_ptr[row];
    const int end = g_row_ptr[row + 1];
    __shared__ int sidx[256];
    float a0 = 0.f, a1 = 0.f, a2 = 0.f, a3 = 0.f;
    for (int base = beg; base < end; base += 256) {
        int cnt = min(256, end - base);
        for (int i = f; i < cnt; i += F) sidx[i] = g_src_sorted[base + i];
        __syncthreads();
        int i = 0;
        for (; i + 4 <= cnt; i += 4) {
            a0 += X[(size_t)sidx[i + 0] * F + f];
            a1 += X[(size_t)sidx[i + 1] * F + f];
            a2 += X[(size_t)sidx[i + 2] * F + f];
            a3 += X[(size_t)sidx[i + 3] * F + f];
        }
        for (; i < cnt; i++) a0 += X[(size_t)sidx[i] * F + f];
        __syncthreads();
    }
    float v = (a0 + a1 + a2 + a3) * g_rs_in[row] + bias[f];
    if (RELU) v = fmaxf(v, 0.f);
    out[(size_t)row * F + f] = v;
}

__global__ void k_spmm1(const float* __restrict__ b1) {
    spmm_body<F_H, true>(&g_A1[0], b1, &g_H[0]);
}
__global__ void k_spmm2(const float* __restrict__ b2, float* __restrict__ out) {
    spmm_body<F_OUT, false>(&g_A2[0], b2, out);
}

// ---------------- launch ----------------
extern "C" void kernel_launch(void* const* d_in, const int* in_sizes, int n_in,
                              void* d_out, int out_size) {
    const float* X   = (const float*)d_in[0];
    const int*   src = (const int*)d_in[1];   // int32 or int64 (detected on device)
    const int*   dst = (const int*)d_in[2];
    const float* W1  = (const float*)d_in[3];
    const float* b1  = (const float*)d_in[4];
    const float* W2  = (const float*)d_in[5];
    const float* b2  = (const float*)d_in[6];
    float* out = (float*)d_out;

    const int NB_NODE = (N_NODES + 255) / 256;
    const int NB_EDGE = (N_EDGES + 255) / 256;

    k_zero_deg<<<NB_NODE, 256>>>();
    k_detect  <<<8, 256>>>(src);
    k_degrees <<<NB_EDGE, 256>>>(src, dst);
    k_rsqrt_deg<<<NB_NODE, 256>>>();
    k_scan<<<1, 1024>>>();
    k_fill<<<NB_EDGE, 256>>>(src, dst);

    dim3 grid1(F_H / 64, (N_NODES + 63) / 64);
    k_gemm1<<<grid1, 256>>>(X, W1);
    k_spmm1<<<N_NODES, F_H>>>(b1);

    dim3 grid2(F_OUT / 64, (N_NODES + 63) / 64);
    k_gemm2<<<grid2, 256>>>(W2);
    k_spmm2<<<N_NODES, F_OUT>>>(b2, out);
}